// round 4
// baseline (speedup 1.0000x reference)
#include <cuda_runtime.h>

// Problem constants (fixed by the reference)
#define BB 16
#define HH 768
#define WW 768
#define KK 512
#define HWSZ (HH * WW)                 // 589824

#define WARPS_PER_BLOCK 8
#define NTHREADS 256
#define F4_PER_HALF 96                 // 384 px per half-row
#define NBULK_WARPS (BB * HH * 2)      // 24576 half-rows
#define NBULK_BLOCKS (NBULK_WARPS / WARPS_PER_BLOCK)   // 3072
#define NBLOCKS_TOTAL (NBULK_BLOCKS + BB)              // 3088 (last 16 do gt-correction)

__device__ float g_p1[NBLOCKS_TOTAL];
__device__ float g_p2[NBLOCKS_TOTAL];

#define FULL 0xffffffffu

__inline__ __device__ float warp_reduce(float v) {
    #pragma unroll
    for (int o = 16; o > 0; o >>= 1) v += __shfl_down_sync(FULL, v, o);
    return v;
}

__global__ void __launch_bounds__(NTHREADS, 3) bulk_kernel(
    const float* __restrict__ pre, const float* __restrict__ gt,
    const int* __restrict__ cors)
{
    const int lane = threadIdx.x & 31;
    const int wid  = threadIdx.x >> 5;
    float s1 = 0.f, s2 = 0.f;

    if (blockIdx.x < NBULK_BLOCKS) {
        // ---- Bulk: one warp per half-row; 12 independent coalesced f4 loads/thread ----
        const int w     = blockIdx.x * WARPS_PER_BLOCK + wid;
        const int half  = w & 1;
        const int grow  = w >> 1;              // global row = b*H + y
        const int y     = grow % HH;
        const int rowbase = grow * WW;
        const int f0    = half * F4_PER_HALF + lane;   // f4 index of slot 0

        const float4* __restrict__ prow = reinterpret_cast<const float4*>(pre + rowbase);
        const float4* __restrict__ gr4  = reinterpret_cast<const float4*>(gt  + rowbase);
        const float4* __restrict__ urow = reinterpret_cast<const float4*>(pre + rowbase - WW);
        const float4* __restrict__ drow = reinterpret_cast<const float4*>(pre + rowbase + WW);
        const bool hasu = (y > 0);
        const bool hasd = (y < HH - 1);
        const float4 z4 = make_float4(0.f, 0.f, 0.f, 0.f);

        float4 c[3], u[3], d[3], g[3];
        #pragma unroll
        for (int k = 0; k < 3; k++) {
            const int idx = f0 + 32 * k;
            c[k] = prow[idx];
            g[k] = gr4[idx];
            u[k] = hasu ? urow[idx] : z4;
            d[k] = hasd ? drow[idx] : z4;
        }

        // seam scalars: lane0 of right half needs px 383; lane31 of left half needs px 384
        float edge = 0.f;
        if (lane == 0 && half == 1)  edge = __ldg(pre + rowbase + F4_PER_HALF * 4 - 1);
        if (lane == 31 && half == 0) edge = __ldg(pre + rowbase + F4_PER_HALF * 4);

        #pragma unroll
        for (int k = 0; k < 3; k++) {
            const float lw = __shfl_up_sync(FULL, c[k].w, 1);    // lane-1's .w
            const float rx = __shfl_down_sync(FULL, c[k].x, 1);  // lane+1's .x
            const float w31_prev = (k > 0) ? __shfl_sync(FULL, c[k - 1].w, 31) : 0.f;
            const float x0_next  = (k < 2) ? __shfl_sync(FULL, c[k + 1].x, 0)  : 0.f;

            const float leftmost  = (lane == 0)
                ? (k > 0 ? w31_prev : (half ? edge : 0.f)) : lw;
            const float rightmost = (lane == 31)
                ? (k < 2 ? x0_next : (half ? 0.f : edge)) : rx;

            const float cv[4] = {c[k].x, c[k].y, c[k].z, c[k].w};
            const float gv[4] = {g[k].x, g[k].y, g[k].z, g[k].w};
            const float uv[4] = {u[k].x, u[k].y, u[k].z, u[k].w};
            const float dv[4] = {d[k].x, d[k].y, d[k].z, d[k].w};
            const float lv[4] = {leftmost, c[k].x, c[k].y, c[k].z};
            const float rv[4] = {c[k].y, c[k].z, c[k].w, rightmost};

            #pragma unroll
            for (int i = 0; i < 4; i++) {
                const float df  = cv[i] - gv[i];
                const float err = df * df;
                const bool pm = (cv[i] > lv[i]) && (cv[i] > rv[i]) &&
                                (cv[i] > uv[i]) && (cv[i] > dv[i]);
                s1 += pm ? err : 0.f;
                s2 += err + (gv[i] > 0.f ? 4.f * err : 0.f);
            }
        }
    } else {
        // ---- gt-point correction: l1 += err*(1 - 2*pre_mask) at UNIQUE gt coords ----
        __shared__ int sx[KK];
        __shared__ int sy[KK];
        const int b = blockIdx.x - NBULK_BLOCKS;
        for (int p = threadIdx.x; p < KK; p += NTHREADS) {
            sx[p] = cors[(b * KK + p) * 2 + 0];
            sy[p] = cors[(b * KK + p) * 2 + 1];
        }
        __syncthreads();
        for (int p = threadIdx.x; p < KK; p += NTHREADS) {
            const int x = sx[p], y = sy[p];
            bool dup = false;
            for (int j = 0; j < p; j++) {
                if (sx[j] == x && sy[j] == y) { dup = true; break; }
            }
            if (!dup) {
                const int base = b * HWSZ + y * WW + x;
                const float cc = pre[base];
                const float l = (x > 0)      ? pre[base - 1]  : 0.f;
                const float r = (x < WW - 1) ? pre[base + 1]  : 0.f;
                const float u = (y > 0)      ? pre[base - WW] : 0.f;
                const float d = (y < HH - 1) ? pre[base + WW] : 0.f;
                const bool pm = (cc > l) && (cc > r) && (cc > u) && (cc > d);
                const float diff = cc - gt[base];
                s1 += (diff * diff) * (pm ? -1.f : 1.f);
            }
        }
    }

    // ---- Block reduction → per-block partial slots (no atomics, no persistent state) ----
    __shared__ float sh1[WARPS_PER_BLOCK], sh2[WARPS_PER_BLOCK];
    s1 = warp_reduce(s1);
    s2 = warp_reduce(s2);
    if (lane == 0) { sh1[wid] = s1; sh2[wid] = s2; }
    __syncthreads();
    if (wid == 0) {
        float v1 = (lane < WARPS_PER_BLOCK) ? sh1[lane] : 0.f;
        float v2 = (lane < WARPS_PER_BLOCK) ? sh2[lane] : 0.f;
        v1 = warp_reduce(v1);
        v2 = warp_reduce(v2);
        if (lane == 0) {
            g_p1[blockIdx.x] = v1;
            g_p2[blockIdx.x] = v2;
        }
    }
}

__inline__ __device__ double warp_reduce_d(double v) {
    #pragma unroll
    for (int o = 16; o > 0; o >>= 1) v += __shfl_down_sync(FULL, v, o);
    return v;
}

__global__ void __launch_bounds__(256) finalize_kernel(float* __restrict__ out) {
    double local = 0.0;
    for (int i = threadIdx.x; i < NBLOCKS_TOTAL; i += 256)
        local += (double)g_p1[i] + (double)g_p2[i];

    __shared__ double sh[8];
    const int lane = threadIdx.x & 31;
    const int wid  = threadIdx.x >> 5;
    local = warp_reduce_d(local);
    if (lane == 0) sh[wid] = local;
    __syncthreads();
    if (wid == 0) {
        double v = (lane < 8) ? sh[lane] : 0.0;
        v = warp_reduce_d(v);
        if (lane == 0) out[0] = (float)(v / (double)BB);
    }
}

extern "C" void kernel_launch(void* const* d_in, const int* in_sizes, int n_in,
                              void* d_out, int out_size)
{
    const float* pre  = (const float*)d_in[0];
    const float* gt   = (const float*)d_in[1];
    const int*   cors = (const int*)d_in[2];
    float*       out  = (float*)d_out;

    bulk_kernel<<<NBLOCKS_TOTAL, NTHREADS>>>(pre, gt, cors);
    finalize_kernel<<<1, 256>>>(out);
}

// round 5
// speedup vs baseline: 1.1437x; 1.1437x over previous
#include <cuda_runtime.h>

// Problem constants (fixed by the reference)
#define BB 16
#define HH 768
#define WW 768
#define KK 512
#define HWSZ (HH * WW)               // 589824
#define VECS_PER_ROW (WW / 4)        // 192
#define TOTAL_VECS (BB * HH * VECS_PER_ROW)   // 2359296

#define NTHREADS 256
#define NBULK_BLOCKS 1152            // 1152*256*8 == TOTAL_VECS exactly
#define GSTRIDE (NBULK_BLOCKS * NTHREADS)     // 294912
#define NITER 8
#define NBLOCKS_TOTAL (NBULK_BLOCKS + BB)     // 1168

// Accumulators: [0]=l1, [1]=l2. Zero at load; finalize resets after each replay.
__device__ double g_acc[2];

#define FULL 0xffffffffu

__inline__ __device__ float warp_reduce(float v) {
    #pragma unroll
    for (int o = 16; o > 0; o >>= 1) v += __shfl_down_sync(FULL, v, o);
    return v;
}

// Process one float4 position; accumulates into s1/s2.
__device__ __forceinline__ void process_vec(
    const float* __restrict__ pre, const float* __restrict__ gt,
    int vec, float& s1, float& s2)
{
    const int row  = vec / VECS_PER_ROW;       // global row (b*H + y)
    const int y    = row % HH;
    const int x0   = (vec - row * VECS_PER_ROW) * 4;
    const int base = vec * 4;                  // == row*W + x0

    const float4 z4 = make_float4(0.f, 0.f, 0.f, 0.f);
    const float4 c  = *reinterpret_cast<const float4*>(pre + base);
    const float4 g  = *reinterpret_cast<const float4*>(gt  + base);
    const float4 up = (y > 0)      ? *reinterpret_cast<const float4*>(pre + base - WW) : z4;
    const float4 dn = (y < HH - 1) ? *reinterpret_cast<const float4*>(pre + base + WW) : z4;
    const float lft = (x0 > 0)      ? __ldg(pre + base - 1) : 0.f;
    const float rgt = (x0 + 4 < WW) ? __ldg(pre + base + 4) : 0.f;

    const float cv[4] = {c.x, c.y, c.z, c.w};
    const float gv[4] = {g.x, g.y, g.z, g.w};
    const float uv[4] = {up.x, up.y, up.z, up.w};
    const float dv[4] = {dn.x, dn.y, dn.z, dn.w};
    const float lv[4] = {lft, c.x, c.y, c.z};
    const float rv[4] = {c.y, c.z, c.w, rgt};

    #pragma unroll
    for (int i = 0; i < 4; i++) {
        const float d   = cv[i] - gv[i];
        const float err = d * d;
        const float nb  = fmaxf(fmaxf(lv[i], rv[i]), fmaxf(uv[i], dv[i]));
        const float w   = (gv[i] > 0.f) ? 5.f : 1.f;
        s1 += (cv[i] > nb) ? err : 0.f;
        s2  = fmaf(w, err, s2);
    }
}

__global__ void __launch_bounds__(NTHREADS) bulk_kernel(
    const float* __restrict__ pre, const float* __restrict__ gt,
    const int* __restrict__ cors)
{
    const int lane = threadIdx.x & 31;
    const int wid  = threadIdx.x >> 5;
    float s1 = 0.f, s2 = 0.f;

    if (blockIdx.x < NBULK_BLOCKS) {
        const int v0 = blockIdx.x * NTHREADS + threadIdx.x;
        // 8 grid-stride positions, two independent ones per unrolled step (MLP x2)
        #pragma unroll
        for (int i = 0; i < NITER; i += 2) {
            process_vec(pre, gt, v0 + i * GSTRIDE,       s1, s2);
            process_vec(pre, gt, v0 + (i + 1) * GSTRIDE, s1, s2);
        }
    } else {
        // gt-point correction: l1 += err*(1 - 2*pre_mask) at UNIQUE gt coords
        __shared__ int sx[KK];
        __shared__ int sy[KK];
        const int b = blockIdx.x - NBULK_BLOCKS;
        for (int p = threadIdx.x; p < KK; p += NTHREADS) {
            sx[p] = cors[(b * KK + p) * 2 + 0];
            sy[p] = cors[(b * KK + p) * 2 + 1];
        }
        __syncthreads();
        for (int p = threadIdx.x; p < KK; p += NTHREADS) {
            const int x = sx[p], y = sy[p];
            bool dup = false;
            for (int j = 0; j < p; j++) {
                if (sx[j] == x && sy[j] == y) { dup = true; break; }
            }
            if (!dup) {
                const int base = b * HWSZ + y * WW + x;
                const float cc = pre[base];
                const float l = (x > 0)      ? pre[base - 1]  : 0.f;
                const float r = (x < WW - 1) ? pre[base + 1]  : 0.f;
                const float u = (y > 0)      ? pre[base - WW] : 0.f;
                const float d = (y < HH - 1) ? pre[base + WW] : 0.f;
                const bool pm = (cc > l) && (cc > r) && (cc > u) && (cc > d);
                const float diff = cc - gt[base];
                s1 += (diff * diff) * (pm ? -1.f : 1.f);
            }
        }
    }

    // Block reduction, then two double atomics per block (L2-coherent, no fence)
    __shared__ float sh1[NTHREADS / 32], sh2[NTHREADS / 32];
    s1 = warp_reduce(s1);
    s2 = warp_reduce(s2);
    if (lane == 0) { sh1[wid] = s1; sh2[wid] = s2; }
    __syncthreads();
    if (wid == 0) {
        float v1 = (lane < NTHREADS / 32) ? sh1[lane] : 0.f;
        float v2 = (lane < NTHREADS / 32) ? sh2[lane] : 0.f;
        v1 = warp_reduce(v1);
        v2 = warp_reduce(v2);
        if (lane == 0) {
            atomicAdd(&g_acc[0], (double)v1);
            atomicAdd(&g_acc[1], (double)v2);
        }
    }
}

// Finalize: write output, then reset accumulators for the next graph replay.
__global__ void finalize_kernel(float* __restrict__ out) {
    if (threadIdx.x == 0) {
        out[0] = (float)((g_acc[0] + g_acc[1]) / (double)BB);
        g_acc[0] = 0.0;
        g_acc[1] = 0.0;
    }
}

extern "C" void kernel_launch(void* const* d_in, const int* in_sizes, int n_in,
                              void* d_out, int out_size)
{
    const float* pre  = (const float*)d_in[0];
    const float* gt   = (const float*)d_in[1];
    const int*   cors = (const int*)d_in[2];
    float*       out  = (float*)d_out;

    bulk_kernel<<<NBLOCKS_TOTAL, NTHREADS>>>(pre, gt, cors);
    finalize_kernel<<<1, 32>>>(out);
}